// round 11
// baseline (speedup 1.0000x reference)
#include <cuda_runtime.h>

// ---------------------------------------------------------------------------
// Problem constants
// ---------------------------------------------------------------------------
#define P_ 64
#define N_ 2048
#define M1_ 512
#define M2_ 128
#define K_ 32

// Output packing offsets (float32 elements, reference tuple order)
#define XG_OFF      0            // [64,768]
#define POSG_OFF    49152        // [64,3] zeros
#define BATCHG_OFF  49344        // [64]
#define X2_OFF      49408        // [8192,384]
#define Q2_OFF      3195136      // [8192,3]
#define BATCH2_OFF  3219712      // [8192]
#define VMIN_OFF    3227904      // [64,3]
#define DIFF_OFF    3228096      // [64]

typedef unsigned long long u64;

// ---------------------------------------------------------------------------
// Scratch (device globals; no allocations allowed)
// ---------------------------------------------------------------------------
__device__ float g_pn   [P_ * N_ * 3];
__device__ float g_q1   [P_ * M1_ * 3];
__device__ int   g_nidx1[P_ * M1_ * K_];
__device__ int   g_cnt1 [P_ * M1_];
__device__ float g_x1   [P_ * M1_ * 128];
__device__ int   g_nidx2[P_ * M2_ * K_];
__device__ int   g_cnt2 [P_ * M2_];

// ---------------------------------------------------------------------------
// f32x2 packed helpers
// ---------------------------------------------------------------------------
__device__ __forceinline__ u64 ffma2(u64 a, u64 b, u64 c) {
    u64 d;
    asm("fma.rn.f32x2 %0, %1, %2, %3;" : "=l"(d) : "l"(a), "l"(b), "l"(c));
    return d;
}
__device__ __forceinline__ u64 pack2(float x, float y) {
    u64 r;
    asm("mov.b64 %0, {%1, %2};" : "=l"(r) : "f"(x), "f"(y));
    return r;
}
__device__ __forceinline__ float2 unpk(u64 v) {
    float2 r;
    asm("mov.b64 {%0, %1}, %2;" : "=f"(r.x), "=f"(r.y) : "l"(v));
    return r;
}

// ---------------------------------------------------------------------------
// Exact (non-fused) squared distance
// ---------------------------------------------------------------------------
__device__ __forceinline__ float dist2e(float ax, float ay, float az,
                                        float bx, float by, float bz) {
    float dx = __fsub_rn(ax, bx);
    float dy = __fsub_rn(ay, by);
    float dz = __fsub_rn(az, bz);
    float s  = __fadd_rn(__fmul_rn(dx, dx), __fmul_rn(dy, dy));
    return __fadd_rn(s, __fmul_rn(dz, dz));
}

// ---------------------------------------------------------------------------
// Kernel 1: per-patch normalization + vmin/diff outputs
// ---------------------------------------------------------------------------
__global__ __launch_bounds__(256) void norm_kernel(const float* __restrict__ pos,
                                                   float* __restrict__ out) {
    int p = blockIdx.x, t = threadIdx.x;
    const float* base = pos + (size_t)p * N_ * 3;

    float mn0 = 3.4e38f, mn1 = 3.4e38f, mn2 = 3.4e38f;
    float mx0 = -3.4e38f, mx1 = -3.4e38f, mx2 = -3.4e38f;
    for (int i = t; i < N_; i += 256) {
        float v0 = base[i * 3 + 0], v1 = base[i * 3 + 1], v2 = base[i * 3 + 2];
        mn0 = fminf(mn0, v0); mx0 = fmaxf(mx0, v0);
        mn1 = fminf(mn1, v1); mx1 = fmaxf(mx1, v1);
        mn2 = fminf(mn2, v2); mx2 = fmaxf(mx2, v2);
    }
#pragma unroll
    for (int o = 16; o; o >>= 1) {
        mn0 = fminf(mn0, __shfl_down_sync(0xffffffffu, mn0, o));
        mn1 = fminf(mn1, __shfl_down_sync(0xffffffffu, mn1, o));
        mn2 = fminf(mn2, __shfl_down_sync(0xffffffffu, mn2, o));
        mx0 = fmaxf(mx0, __shfl_down_sync(0xffffffffu, mx0, o));
        mx1 = fmaxf(mx1, __shfl_down_sync(0xffffffffu, mx1, o));
        mx2 = fmaxf(mx2, __shfl_down_sync(0xffffffffu, mx2, o));
    }
    __shared__ float s6[8][6];
    if ((t & 31) == 0) {
        int w = t >> 5;
        s6[w][0] = mn0; s6[w][1] = mn1; s6[w][2] = mn2;
        s6[w][3] = mx0; s6[w][4] = mx1; s6[w][5] = mx2;
    }
    __syncthreads();
    __shared__ float fin[4];
    if (t == 0) {
        float a0 = s6[0][0], a1 = s6[0][1], a2 = s6[0][2];
        float b0 = s6[0][3], b1 = s6[0][4], b2 = s6[0][5];
        for (int w = 1; w < 8; w++) {
            a0 = fminf(a0, s6[w][0]); a1 = fminf(a1, s6[w][1]); a2 = fminf(a2, s6[w][2]);
            b0 = fmaxf(b0, s6[w][3]); b1 = fmaxf(b1, s6[w][4]); b2 = fmaxf(b2, s6[w][5]);
        }
        float d0 = __fsub_rn(b0, a0), d1 = __fsub_rn(b1, a1), d2 = __fsub_rn(b2, a2);
        float diff = fmaxf(fmaxf(d0, d1), d2);
        fin[0] = a0; fin[1] = a1; fin[2] = a2; fin[3] = diff;
        out[VMIN_OFF + p * 3 + 0] = a0;
        out[VMIN_OFF + p * 3 + 1] = a1;
        out[VMIN_OFF + p * 3 + 2] = a2;
        out[DIFF_OFF + p] = diff;
    }
    __syncthreads();
    float vx = fin[0], vy = fin[1], vz = fin[2], df = fin[3];
    for (int i = t; i < N_; i += 256) {
        float* o3 = g_pn + ((size_t)p * N_ + i) * 3;
        o3[0] = __fdiv_rn(__fsub_rn(base[i * 3 + 0], vx), df);
        o3[1] = __fdiv_rn(__fsub_rn(base[i * 3 + 1], vy), df);
        o3[2] = __fdiv_rn(__fsub_rn(base[i * 3 + 2], vz), df);
    }
}

// ---------------------------------------------------------------------------
// Kernel 1b: small pass-through outputs
// ---------------------------------------------------------------------------
__global__ __launch_bounds__(256) void aux_kernel(float* __restrict__ out) {
    int p = blockIdx.x, t = threadIdx.x;
    if (t < 3) out[POSG_OFF + p * 3 + t] = 0.0f;
    if (t == 0) out[BATCHG_OFF + p] = (float)p;
    for (int i = t; i < M2_; i += 256) out[BATCH2_OFF + p * M2_ + i] = (float)p;
    for (int i = t; i < 768; i += 256) out[XG_OFF + p * 768 + i] = 0.0f;
}

// ---------------------------------------------------------------------------
// Kernel 2: FPS — REDUX-based argmax, 256 threads.
// ---------------------------------------------------------------------------
template <int NPTS, int M>
__global__ __launch_bounds__(256) void fps_kernel(int src_sel, float* q_ext) {
    constexpr int T = 256;
    constexpr int U = NPTS / T;
    __shared__ float spx[NPTS], spy[NPTS], spz[NPTS];
    __shared__ u64 wred[8];
    __shared__ int sj;
    int p = blockIdx.x, t = threadIdx.x;
    const float* base = (src_sel ? g_q1 : g_pn) + (size_t)p * NPTS * 3;
    float* q_out = (q_ext ? q_ext : g_q1) + (size_t)p * M * 3;
    for (int i = t; i < NPTS; i += T) {
        spx[i] = base[i * 3 + 0];
        spy[i] = base[i * 3 + 1];
        spz[i] = base[i * 3 + 2];
    }
    __syncthreads();
    float mx[U], my[U], mz[U], d[U];
    float x0 = spx[0], y0 = spy[0], z0 = spz[0];
#pragma unroll
    for (int u = 0; u < U; u++) {
        int i = t + u * T;
        mx[u] = spx[i]; my[u] = spy[i]; mz[u] = spz[i];
        d[u] = dist2e(mx[u], my[u], mz[u], x0, y0, z0);
    }
    if (t == 0) { q_out[0] = x0; q_out[1] = y0; q_out[2] = z0; }
    for (int it = 1; it < M; it++) {
        float bd = d[0]; int bi = t;
#pragma unroll
        for (int u = 1; u < U; u++) {
            if (d[u] > bd) { bd = d[u]; bi = t + u * T; }
        }
        unsigned mb = __reduce_max_sync(0xffffffffu, __float_as_uint(bd));
        int cand = (__float_as_uint(bd) == mb) ? bi : 0x7fffffff;
        int mi = __reduce_min_sync(0xffffffffu, cand);
        if ((t & 31) == 0)
            wred[t >> 5] = ((u64)mb << 32) | (unsigned)(NPTS - mi);
        __syncthreads();
        if (t < 32) {
            u64 b = (t < 8) ? wred[t] : 0ull;
#pragma unroll
            for (int o = 4; o; o >>= 1) {
                u64 v = __shfl_down_sync(0xffffffffu, b, o);
                if (v > b) b = v;
            }
            if (t == 0) sj = NPTS - (int)(unsigned)(b & 0xffffffffull);
        }
        __syncthreads();
        int j = sj;
        float jx = spx[j], jy = spy[j], jz = spz[j];
        if (t == 0) {
            q_out[it * 3 + 0] = jx; q_out[it * 3 + 1] = jy; q_out[it * 3 + 2] = jz;
        }
#pragma unroll
        for (int u = 0; u < U; u++) {
            float nd = dist2e(mx[u], my[u], mz[u], jx, jy, jz);
            d[u] = fminf(d[u], nd);
        }
    }
}

// ---------------------------------------------------------------------------
// Kernel 3: radius top-K — branchless register top-K (no local memory).
// ---------------------------------------------------------------------------
template <int NPTS>
__global__ void nbr_kernel(int src_sel, const float* __restrict__ q_ext,
                           int nq, float r2, int lvl) {
    __shared__ float spx[NPTS], spy[NPTS], spz[NPTS];
    int p = blockIdx.x, t = threadIdx.x;
    const float* base = (src_sel ? g_q1 : g_pn) + (size_t)p * NPTS * 3;
    const float* q = (q_ext ? q_ext : g_q1);
    int* nidx = lvl ? g_nidx2 : g_nidx1;
    int* ncnt = lvl ? g_cnt2 : g_cnt1;
    for (int i = t; i < NPTS; i += blockDim.x) {
        spx[i] = base[i * 3 + 0];
        spy[i] = base[i * 3 + 1];
        spz[i] = base[i * 3 + 2];
    }
    __syncthreads();
    if (t >= nq) return;
    const float* qq = q + ((size_t)p * nq + t) * 3;
    float qx = qq[0], qy = qq[1], qz = qq[2];

    float da[K_];
    int ia[K_];
#pragma unroll
    for (int k = 0; k < K_; k++) { da[k] = 3.4e38f; ia[k] = 0; }
    int cnt = 0;
    float maxd = 3.4e38f;
    int maxslot = 0;

    for (int j = 0; j < NPTS; j++) {
        float d2 = dist2e(spx[j], spy[j], spz[j], qx, qy, qz);
        if (d2 <= r2) {
            if (cnt < K_) {
#pragma unroll
                for (int k = 0; k < K_; k++)
                    if (k == cnt) { da[k] = d2; ia[k] = j; }
                cnt++;
                if (cnt == K_) {
                    float bd = da[0]; int bj = ia[0]; int bs = 0;
#pragma unroll
                    for (int k = 1; k < K_; k++) {
                        bool g = (da[k] > bd) || (da[k] == bd && ia[k] > bj);
                        if (g) { bd = da[k]; bj = ia[k]; bs = k; }
                    }
                    maxd = bd; maxslot = bs;
                }
            } else if (d2 < maxd) {
#pragma unroll
                for (int k = 0; k < K_; k++)
                    if (k == maxslot) { da[k] = d2; ia[k] = j; }
                float bd = da[0]; int bj = ia[0]; int bs = 0;
#pragma unroll
                for (int k = 1; k < K_; k++) {
                    bool g = (da[k] > bd) || (da[k] == bd && ia[k] > bj);
                    if (g) { bd = da[k]; bj = ia[k]; bs = k; }
                }
                maxd = bd; maxslot = bs;
            }
        }
    }
    int* outp = nidx + ((size_t)p * nq + t) * K_;
#pragma unroll
    for (int k = 0; k < K_; k++) outp[k] = (k < cnt) ? ia[k] : 0;
    ncnt[(size_t)p * nq + t] = cnt;
}

// ---------------------------------------------------------------------------
// Kernel 4: MLP1 (6 -> 64 relu -> 128 relu) + masked max — mlp2 template.
// Block = 4 queries, 256 threads. Per query: 64 threads.
// Layer1: thread = (ch-pair of 32, neighbor-half) -> 64 tasks, 1 pass.
// Layer2: thread = (ch-pair of 64, neighbor-half) -> 128 tasks, 2 passes.
// Weights LDG-coalesced (lane=channel-pair), features LDS-broadcast.
// ---------------------------------------------------------------------------
__global__ __launch_bounds__(256, 3) void mlp1_kernel(const float* __restrict__ W1a,
                                                      const float* __restrict__ b1a,
                                                      const float* __restrict__ W1b,
                                                      const float* __restrict__ b1b) {
    __shared__ __align__(16) float featT[4 * 6 * 36];    // [lq][i][36]
    __shared__ __align__(16) float h1T[4 * 64 * 36];     // [lq][i][36]
    __shared__ float red[4 * 128 * 2];                   // [lq][c][half]
    __shared__ int scnt[4];
    int b = blockIdx.x, t = threadIdx.x;
    int q0 = b * 4;
    int lq = t >> 6, w = t & 63;
    if (t < 4) scnt[t] = g_cnt1[q0 + t];
    // fill features: 4q x 32k x 6i = 768 elements
    for (int e = t; e < 768; e += 256) {
        int eq = e / 192;
        int rem = e - eq * 192;
        int k = rem / 6, i = rem - k * 6;
        int gq = q0 + eq;
        int p = gq >> 9;
        int j = g_nidx1[(size_t)gq * K_ + k];
        const float* pj = g_pn + ((size_t)p * N_ + j) * 3;
        float v;
        if (i < 3) v = pj[i];
        else       v = pj[i - 3] - g_q1[(size_t)gq * 3 + (i - 3)];
        featT[(eq * 6 + i) * 36 + k] = v;
    }
    __syncthreads();
    // ---- layer 1: 32 ch-pairs x 2 halves per query ----
    {
        int cp = w & 31, h = w >> 5;
        int c0 = 2 * cp, koff = h * 16;
        float2 bp = *(const float2*)&b1a[c0];
        u64 a0[8], a1[8];
        u64 bx = pack2(bp.x, bp.x), by = pack2(bp.y, bp.y);
#pragma unroll
        for (int m = 0; m < 8; m++) { a0[m] = bx; a1[m] = by; }
#pragma unroll
        for (int i = 0; i < 6; i++) {
            float2 wv = *(const float2*)&W1a[i * 64 + c0];
            u64 w0 = pack2(wv.x, wv.x), w1 = pack2(wv.y, wv.y);
            const ulonglong2* fr = (const ulonglong2*)&featT[(lq * 6 + i) * 36 + koff];
            ulonglong2 fA = fr[0], fB = fr[1], fC = fr[2], fD = fr[3];
            a0[0] = ffma2(fA.x, w0, a0[0]); a0[1] = ffma2(fA.y, w0, a0[1]);
            a0[2] = ffma2(fB.x, w0, a0[2]); a0[3] = ffma2(fB.y, w0, a0[3]);
            a0[4] = ffma2(fC.x, w0, a0[4]); a0[5] = ffma2(fC.y, w0, a0[5]);
            a0[6] = ffma2(fD.x, w0, a0[6]); a0[7] = ffma2(fD.y, w0, a0[7]);
            a1[0] = ffma2(fA.x, w1, a1[0]); a1[1] = ffma2(fA.y, w1, a1[1]);
            a1[2] = ffma2(fB.x, w1, a1[2]); a1[3] = ffma2(fB.y, w1, a1[3]);
            a1[4] = ffma2(fC.x, w1, a1[4]); a1[5] = ffma2(fC.y, w1, a1[5]);
            a1[6] = ffma2(fD.x, w1, a1[6]); a1[7] = ffma2(fD.y, w1, a1[7]);
        }
        float4* h0 = (float4*)&h1T[(lq * 64 + c0) * 36 + koff];
        float4* h1 = (float4*)&h1T[(lq * 64 + c0 + 1) * 36 + koff];
#pragma unroll
        for (int mm = 0; mm < 4; mm++) {
            float2 u0 = unpk(a0[2 * mm]), u1 = unpk(a0[2 * mm + 1]);
            h0[mm] = make_float4(fmaxf(u0.x, 0.f), fmaxf(u0.y, 0.f),
                                 fmaxf(u1.x, 0.f), fmaxf(u1.y, 0.f));
            float2 v0 = unpk(a1[2 * mm]), v1 = unpk(a1[2 * mm + 1]);
            h1[mm] = make_float4(fmaxf(v0.x, 0.f), fmaxf(v0.y, 0.f),
                                 fmaxf(v1.x, 0.f), fmaxf(v1.y, 0.f));
        }
    }
    __syncthreads();
    // ---- layer 2: 64 ch-pairs x 2 halves per query, 2 passes ----
    int cnt = scnt[lq];
#pragma unroll 1
    for (int pass = 0; pass < 2; pass++) {
        int cp = (w & 31) + pass * 32, h = w >> 5;
        int c0 = 2 * cp, koff = h * 16;
        float2 bp = *(const float2*)&b1b[c0];
        u64 a0[8], a1[8];
        u64 bx = pack2(bp.x, bp.x), by = pack2(bp.y, bp.y);
#pragma unroll
        for (int m = 0; m < 8; m++) { a0[m] = bx; a1[m] = by; }
#pragma unroll 2
        for (int i = 0; i < 64; i++) {
            float2 wv = *(const float2*)&W1b[i * 128 + c0];
            u64 w0 = pack2(wv.x, wv.x), w1 = pack2(wv.y, wv.y);
            const ulonglong2* fr = (const ulonglong2*)&h1T[(lq * 64 + i) * 36 + koff];
            ulonglong2 fA = fr[0], fB = fr[1], fC = fr[2], fD = fr[3];
            a0[0] = ffma2(fA.x, w0, a0[0]); a0[1] = ffma2(fA.y, w0, a0[1]);
            a0[2] = ffma2(fB.x, w0, a0[2]); a0[3] = ffma2(fB.y, w0, a0[3]);
            a0[4] = ffma2(fC.x, w0, a0[4]); a0[5] = ffma2(fC.y, w0, a0[5]);
            a0[6] = ffma2(fD.x, w0, a0[6]); a0[7] = ffma2(fD.y, w0, a0[7]);
            a1[0] = ffma2(fA.x, w1, a1[0]); a1[1] = ffma2(fA.y, w1, a1[1]);
            a1[2] = ffma2(fB.x, w1, a1[2]); a1[3] = ffma2(fB.y, w1, a1[3]);
            a1[4] = ffma2(fC.x, w1, a1[4]); a1[5] = ffma2(fC.y, w1, a1[5]);
            a1[6] = ffma2(fD.x, w1, a1[6]); a1[7] = ffma2(fD.y, w1, a1[7]);
        }
        float m0 = 0.f, m1 = 0.f;
#pragma unroll
        for (int m = 0; m < 8; m++) {
            int k0 = koff + 2 * m, k1 = koff + 2 * m + 1;
            float2 u0 = unpk(a0[m]), u1 = unpk(a1[m]);
            if (k0 < cnt) { m0 = fmaxf(m0, fmaxf(u0.x, 0.f)); m1 = fmaxf(m1, fmaxf(u1.x, 0.f)); }
            if (k1 < cnt) { m0 = fmaxf(m0, fmaxf(u0.y, 0.f)); m1 = fmaxf(m1, fmaxf(u1.y, 0.f)); }
        }
        red[(lq * 128 + c0) * 2 + h]     = m0;
        red[(lq * 128 + c0 + 1) * 2 + h] = m1;
    }
    __syncthreads();
    for (int e = t; e < 512; e += 256) {
        int eq = e >> 7, c = e & 127;
        g_x1[(size_t)(q0 + eq) * 128 + c] =
            fmaxf(red[(eq * 128 + c) * 2], red[(eq * 128 + c) * 2 + 1]);
    }
}

// ---------------------------------------------------------------------------
// Kernel 5: MLP2 (131 -> 256 relu -> 384 relu) + masked max.
// Thread = (channel-pair, 16-neighbor half). Unroll 2 for LDG/LDS batching.
// red aliased onto dead featT region (smem 55.7KB).
// ---------------------------------------------------------------------------
#define MLP2_SMEM ((131 + 256) * 36 * 4)
__global__ __launch_bounds__(256, 3) void mlp2_kernel(const float* __restrict__ q2,
                                                      const float* __restrict__ W2a,
                                                      const float* __restrict__ b2a,
                                                      const float* __restrict__ W2b,
                                                      const float* __restrict__ b2b,
                                                      float* __restrict__ out) {
    extern __shared__ __align__(16) float sm[];
    float* featT = sm;               // [131][36] (k-minor); dead after layer 1
    float* h1T   = sm + 131 * 36;    // [256][36]
    float* red   = sm;               // [384][2] aliased onto featT region
    int q = blockIdx.x;
    int p = q >> 7;
    int t = threadIdx.x;
    int cnt = g_cnt2[q];
    int base_q1 = p * M1_;
    float q2x = q2[q * 3 + 0], q2y = q2[q * 3 + 1], q2z = q2[q * 3 + 2];
    for (int e = t; e < K_ * 131; e += 256) {
        int k = e / 131, i = e - k * 131;
        int j = g_nidx2[q * K_ + k];
        float v;
        if (i < 128) {
            v = g_x1[((size_t)(base_q1 + j)) * 128 + i];
        } else {
            float c = (i == 128) ? q2x : (i == 129) ? q2y : q2z;
            v = g_q1[((size_t)(base_q1 + j)) * 3 + (i - 128)] - c;
        }
        featT[i * 36 + k] = v;
    }
    __syncthreads();
    // -------- layer 1: 256 threads = 128 ch-pairs x 2 neighbor-halves ------
    {
        int cp = t & 127, h = t >> 7;
        int c0 = 2 * cp, koff = h * 16;
        float2 bp = *(const float2*)&b2a[c0];
        u64 a0[8], a1[8];
        u64 bx = pack2(bp.x, bp.x), by = pack2(bp.y, bp.y);
#pragma unroll
        for (int m = 0; m < 8; m++) { a0[m] = bx; a1[m] = by; }
#pragma unroll 2
        for (int i = 0; i < 131; i++) {
            float2 wv = *(const float2*)&W2a[i * 256 + c0];
            u64 w0 = pack2(wv.x, wv.x), w1 = pack2(wv.y, wv.y);
            const ulonglong2* fr = (const ulonglong2*)&featT[i * 36 + koff];
            ulonglong2 fA = fr[0], fB = fr[1], fC = fr[2], fD = fr[3];
            a0[0] = ffma2(fA.x, w0, a0[0]); a0[1] = ffma2(fA.y, w0, a0[1]);
            a0[2] = ffma2(fB.x, w0, a0[2]); a0[3] = ffma2(fB.y, w0, a0[3]);
            a0[4] = ffma2(fC.x, w0, a0[4]); a0[5] = ffma2(fC.y, w0, a0[5]);
            a0[6] = ffma2(fD.x, w0, a0[6]); a0[7] = ffma2(fD.y, w0, a0[7]);
            a1[0] = ffma2(fA.x, w1, a1[0]); a1[1] = ffma2(fA.y, w1, a1[1]);
            a1[2] = ffma2(fB.x, w1, a1[2]); a1[3] = ffma2(fB.y, w1, a1[3]);
            a1[4] = ffma2(fC.x, w1, a1[4]); a1[5] = ffma2(fC.y, w1, a1[5]);
            a1[6] = ffma2(fD.x, w1, a1[6]); a1[7] = ffma2(fD.y, w1, a1[7]);
        }
        float4* h0 = (float4*)&h1T[c0 * 36 + koff];
        float4* h1 = (float4*)&h1T[(c0 + 1) * 36 + koff];
#pragma unroll
        for (int mm = 0; mm < 4; mm++) {
            float2 u0 = unpk(a0[2 * mm]), u1 = unpk(a0[2 * mm + 1]);
            h0[mm] = make_float4(fmaxf(u0.x, 0.f), fmaxf(u0.y, 0.f),
                                 fmaxf(u1.x, 0.f), fmaxf(u1.y, 0.f));
            float2 v0 = unpk(a1[2 * mm]), v1 = unpk(a1[2 * mm + 1]);
            h1[mm] = make_float4(fmaxf(v0.x, 0.f), fmaxf(v0.y, 0.f),
                                 fmaxf(v1.x, 0.f), fmaxf(v1.y, 0.f));
        }
    }
    __syncthreads();
    // -------- layer 2: pass A (ch 0..255) + pass B (ch 256..383) -----------
#pragma unroll 1
    for (int pass = 0; pass < 2; pass++) {
        int active = pass == 0 ? 256 : 128;
        if (t < active) {
            int cp, h;
            if (pass == 0) { cp = t & 127; h = t >> 7; }
            else           { cp = t & 63;  h = t >> 6; }
            int c0 = pass * 256 + 2 * cp, koff = h * 16;
            float2 bp = *(const float2*)&b2b[c0];
            u64 a0[8], a1[8];
            u64 bx = pack2(bp.x, bp.x), by = pack2(bp.y, bp.y);
#pragma unroll
            for (int m = 0; m < 8; m++) { a0[m] = bx; a1[m] = by; }
#pragma unroll 2
            for (int i = 0; i < 256; i++) {
                float2 wv = *(const float2*)&W2b[i * 384 + c0];
                u64 w0 = pack2(wv.x, wv.x), w1 = pack2(wv.y, wv.y);
                const ulonglong2* fr = (const ulonglong2*)&h1T[i * 36 + koff];
                ulonglong2 fA = fr[0], fB = fr[1], fC = fr[2], fD = fr[3];
                a0[0] = ffma2(fA.x, w0, a0[0]); a0[1] = ffma2(fA.y, w0, a0[1]);
                a0[2] = ffma2(fB.x, w0, a0[2]); a0[3] = ffma2(fB.y, w0, a0[3]);
                a0[4] = ffma2(fC.x, w0, a0[4]); a0[5] = ffma2(fC.y, w0, a0[5]);
                a0[6] = ffma2(fD.x, w0, a0[6]); a0[7] = ffma2(fD.y, w0, a0[7]);
                a1[0] = ffma2(fA.x, w1, a1[0]); a1[1] = ffma2(fA.y, w1, a1[1]);
                a1[2] = ffma2(fB.x, w1, a1[2]); a1[3] = ffma2(fB.y, w1, a1[3]);
                a1[4] = ffma2(fC.x, w1, a1[4]); a1[5] = ffma2(fC.y, w1, a1[5]);
                a1[6] = ffma2(fD.x, w1, a1[6]); a1[7] = ffma2(fD.y, w1, a1[7]);
            }
            float m0 = 0.f, m1 = 0.f;
#pragma unroll
            for (int m = 0; m < 8; m++) {
                int k0 = koff + 2 * m, k1 = koff + 2 * m + 1;
                float2 u0 = unpk(a0[m]), u1 = unpk(a1[m]);
                if (k0 < cnt) { m0 = fmaxf(m0, fmaxf(u0.x, 0.f)); m1 = fmaxf(m1, fmaxf(u1.x, 0.f)); }
                if (k1 < cnt) { m0 = fmaxf(m0, fmaxf(u0.y, 0.f)); m1 = fmaxf(m1, fmaxf(u1.y, 0.f)); }
            }
            red[c0 * 2 + h]       = m0;
            red[(c0 + 1) * 2 + h] = m1;
        }
    }
    __syncthreads();
    for (int e = t; e < 384; e += 256)
        out[X2_OFF + (size_t)q * 384 + e] = fmaxf(red[e * 2], red[e * 2 + 1]);
}

// ---------------------------------------------------------------------------
// Kernel 6: MLP3 (387 -> 512 relu -> 768 relu) + global max pool via atomics
// ---------------------------------------------------------------------------
__global__ __launch_bounds__(256) void mlp3_kernel(const float* __restrict__ W3a,
                                                   const float* __restrict__ b3a,
                                                   const float* __restrict__ W3b,
                                                   const float* __restrict__ b3b,
                                                   float* __restrict__ out) {
    __shared__ __align__(16) float featT[387 * 8];
    __shared__ __align__(16) float hT[512 * 8];
    int b = blockIdx.x, t = threadIdx.x;
    int qbase = b * 8;
    int p = qbase >> 7;
    for (int e = t; e < 8 * 387; e += 256) {
        int qq = e / 387, i = e - qq * 387;
        int q = qbase + qq;
        float v = (i < 384) ? out[X2_OFF + (size_t)q * 384 + i]
                            : out[Q2_OFF + (size_t)q * 3 + (i - 384)];
        featT[i * 8 + qq] = v;
    }
    __syncthreads();
    {
        float bc0 = b3a[t], bc1 = b3a[t + 256];
        u64 s0[4], s1[4];
        u64 p0 = pack2(bc0, bc0), p1 = pack2(bc1, bc1);
#pragma unroll
        for (int m = 0; m < 4; m++) { s0[m] = p0; s1[m] = p1; }
#pragma unroll 2
        for (int i = 0; i < 387; i++) {
            float w0f = W3a[i * 512 + t];
            float w1f = W3a[i * 512 + t + 256];
            u64 w0 = pack2(w0f, w0f), w1 = pack2(w1f, w1f);
            const ulonglong2* fr = (const ulonglong2*)&featT[i * 8];
            ulonglong2 fa = fr[0], fb = fr[1];
            s0[0] = ffma2(fa.x, w0, s0[0]); s0[1] = ffma2(fa.y, w0, s0[1]);
            s0[2] = ffma2(fb.x, w0, s0[2]); s0[3] = ffma2(fb.y, w0, s0[3]);
            s1[0] = ffma2(fa.x, w1, s1[0]); s1[1] = ffma2(fa.y, w1, s1[1]);
            s1[2] = ffma2(fb.x, w1, s1[2]); s1[3] = ffma2(fb.y, w1, s1[3]);
        }
        float4* h0 = (float4*)&hT[t * 8];
        float4* h1 = (float4*)&hT[(t + 256) * 8];
        {
            float2 u0 = unpk(s0[0]), u1 = unpk(s0[1]), u2 = unpk(s0[2]), u3 = unpk(s0[3]);
            h0[0] = make_float4(fmaxf(u0.x, 0.f), fmaxf(u0.y, 0.f), fmaxf(u1.x, 0.f), fmaxf(u1.y, 0.f));
            h0[1] = make_float4(fmaxf(u2.x, 0.f), fmaxf(u2.y, 0.f), fmaxf(u3.x, 0.f), fmaxf(u3.y, 0.f));
        }
        {
            float2 u0 = unpk(s1[0]), u1 = unpk(s1[1]), u2 = unpk(s1[2]), u3 = unpk(s1[3]);
            h1[0] = make_float4(fmaxf(u0.x, 0.f), fmaxf(u0.y, 0.f), fmaxf(u1.x, 0.f), fmaxf(u1.y, 0.f));
            h1[1] = make_float4(fmaxf(u2.x, 0.f), fmaxf(u2.y, 0.f), fmaxf(u3.x, 0.f), fmaxf(u3.y, 0.f));
        }
    }
    __syncthreads();
    {
        float bc0 = b3b[t], bc1 = b3b[t + 256], bc2 = b3b[t + 512];
        u64 s0[4], s1[4], s2[4];
        u64 p0 = pack2(bc0, bc0), p1 = pack2(bc1, bc1), p2 = pack2(bc2, bc2);
#pragma unroll
        for (int m = 0; m < 4; m++) { s0[m] = p0; s1[m] = p1; s2[m] = p2; }
#pragma unroll 2
        for (int i = 0; i < 512; i++) {
            float w0f = W3b[i * 768 + t];
            float w1f = W3b[i * 768 + t + 256];
            float w2f = W3b[i * 768 + t + 512];
            u64 w0 = pack2(w0f, w0f), w1 = pack2(w1f, w1f), w2 = pack2(w2f, w2f);
            const ulonglong2* hr = (const ulonglong2*)&hT[i * 8];
            ulonglong2 fa = hr[0], fb = hr[1];
            s0[0] = ffma2(fa.x, w0, s0[0]); s0[1] = ffma2(fa.y, w0, s0[1]);
            s0[2] = ffma2(fb.x, w0, s0[2]); s0[3] = ffma2(fb.y, w0, s0[3]);
            s1[0] = ffma2(fa.x, w1, s1[0]); s1[1] = ffma2(fa.y, w1, s1[1]);
            s1[2] = ffma2(fb.x, w1, s1[2]); s1[3] = ffma2(fb.y, w1, s1[3]);
            s2[0] = ffma2(fa.x, w2, s2[0]); s2[1] = ffma2(fa.y, w2, s2[1]);
            s2[2] = ffma2(fb.x, w2, s2[2]); s2[3] = ffma2(fb.y, w2, s2[3]);
        }
        float m0 = 0.f, m1 = 0.f, m2 = 0.f;
#pragma unroll
        for (int m = 0; m < 4; m++) {
            float2 u0 = unpk(s0[m]), u1 = unpk(s1[m]), u2 = unpk(s2[m]);
            m0 = fmaxf(m0, fmaxf(fmaxf(u0.x, 0.f), fmaxf(u0.y, 0.f)));
            m1 = fmaxf(m1, fmaxf(fmaxf(u1.x, 0.f), fmaxf(u1.y, 0.f)));
            m2 = fmaxf(m2, fmaxf(fmaxf(u2.x, 0.f), fmaxf(u2.y, 0.f)));
        }
        atomicMax((unsigned*)&out[XG_OFF + (size_t)p * 768 + t], __float_as_uint(m0));
        atomicMax((unsigned*)&out[XG_OFF + (size_t)p * 768 + t + 256], __float_as_uint(m1));
        atomicMax((unsigned*)&out[XG_OFF + (size_t)p * 768 + t + 512], __float_as_uint(m2));
    }
}

// ---------------------------------------------------------------------------
// Launch. ncu profiles launch index 3 -> mlp2 instrumentation dup (grid 592).
// Its output region is fully overwritten by the real mlp2 launch afterwards.
// ---------------------------------------------------------------------------
extern "C" void kernel_launch(void* const* d_in, const int* in_sizes, int n_in,
                              void* d_out, int out_size) {
    const float* pos = (const float*)d_in[0];
    const float* W1a = (const float*)d_in[2];
    const float* b1a = (const float*)d_in[3];
    const float* W1b = (const float*)d_in[4];
    const float* b1b = (const float*)d_in[5];
    const float* W2a = (const float*)d_in[6];
    const float* b2a = (const float*)d_in[7];
    const float* W2b = (const float*)d_in[8];
    const float* b2b = (const float*)d_in[9];
    const float* W3a = (const float*)d_in[10];
    const float* b3a = (const float*)d_in[11];
    const float* W3b = (const float*)d_in[12];
    const float* b3b = (const float*)d_in[13];
    float* out = (float*)d_out;

    const float R1SQ = (float)(0.15 * 0.15);
    const float R2SQ = (float)(0.3 * 0.3);

    static bool attr_set = false;
    if (!attr_set) {
        cudaFuncSetAttribute(mlp2_kernel, cudaFuncAttributeMaxDynamicSharedMemorySize,
                             MLP2_SMEM);
        attr_set = true;
    }

    norm_kernel<<<P_, 256>>>(pos, out);                              // 0
    aux_kernel<<<P_, 256>>>(out);                                    // 1
    fps_kernel<N_, M1_><<<P_, 256>>>(0, nullptr);                    // 2
    // 3: instrumentation dup of mlp2 <- profiled by ncu
    mlp2_kernel<<<592, 256, MLP2_SMEM>>>(out + Q2_OFF, W2a, b2a, W2b, b2b, out);
    nbr_kernel<N_><<<P_, 512>>>(0, nullptr, M1_, R1SQ, 0);           // 4
    mlp1_kernel<<<P_ * M1_ / 4, 256>>>(W1a, b1a, W1b, b1b);          // 5
    fps_kernel<M1_, M2_><<<P_, 256>>>(1, out + Q2_OFF);              // 6
    nbr_kernel<M1_><<<P_, 128>>>(1, out + Q2_OFF, M2_, R2SQ, 1);     // 7
    mlp2_kernel<<<P_ * M2_, 256, MLP2_SMEM>>>(out + Q2_OFF, W2a, b2a, W2b, b2b, out); // 8
    mlp3_kernel<<<P_ * M2_ / 8, 256>>>(W3a, b3a, W3b, b3b, out);     // 9
}

// round 12
// speedup vs baseline: 1.0822x; 1.0822x over previous
#include <cuda_runtime.h>

// ---------------------------------------------------------------------------
// Problem constants
// ---------------------------------------------------------------------------
#define P_ 64
#define N_ 2048
#define M1_ 512
#define M2_ 128
#define K_ 32

// Output packing offsets (float32 elements, reference tuple order)
#define XG_OFF      0            // [64,768]
#define POSG_OFF    49152        // [64,3] zeros
#define BATCHG_OFF  49344        // [64]
#define X2_OFF      49408        // [8192,384]
#define Q2_OFF      3195136      // [8192,3]
#define BATCH2_OFF  3219712      // [8192]
#define VMIN_OFF    3227904      // [64,3]
#define DIFF_OFF    3228096      // [64]

typedef unsigned long long u64;

// ---------------------------------------------------------------------------
// Scratch (device globals; no allocations allowed)
// ---------------------------------------------------------------------------
__device__ float g_pn   [P_ * N_ * 3];
__device__ float g_q1   [P_ * M1_ * 3];
__device__ int   g_nidx1[P_ * M1_ * K_];
__device__ int   g_cnt1 [P_ * M1_];
__device__ float g_x1   [P_ * M1_ * 128];
__device__ int   g_nidx2[P_ * M2_ * K_];
__device__ int   g_cnt2 [P_ * M2_];

// ---------------------------------------------------------------------------
// f32x2 packed helpers
// ---------------------------------------------------------------------------
__device__ __forceinline__ u64 ffma2(u64 a, u64 b, u64 c) {
    u64 d;
    asm("fma.rn.f32x2 %0, %1, %2, %3;" : "=l"(d) : "l"(a), "l"(b), "l"(c));
    return d;
}
__device__ __forceinline__ u64 pack2(float x, float y) {
    u64 r;
    asm("mov.b64 %0, {%1, %2};" : "=l"(r) : "f"(x), "f"(y));
    return r;
}
__device__ __forceinline__ float2 unpk(u64 v) {
    float2 r;
    asm("mov.b64 {%0, %1}, %2;" : "=f"(r.x), "=f"(r.y) : "l"(v));
    return r;
}

// ---------------------------------------------------------------------------
// Exact (non-fused) squared distance
// ---------------------------------------------------------------------------
__device__ __forceinline__ float dist2e(float ax, float ay, float az,
                                        float bx, float by, float bz) {
    float dx = __fsub_rn(ax, bx);
    float dy = __fsub_rn(ay, by);
    float dz = __fsub_rn(az, bz);
    float s  = __fadd_rn(__fmul_rn(dx, dx), __fmul_rn(dy, dy));
    return __fadd_rn(s, __fmul_rn(dz, dz));
}

// ---------------------------------------------------------------------------
// Kernel 1: per-patch normalization + vmin/diff outputs
// ---------------------------------------------------------------------------
__global__ __launch_bounds__(256) void norm_kernel(const float* __restrict__ pos,
                                                   float* __restrict__ out) {
    int p = blockIdx.x, t = threadIdx.x;
    const float* base = pos + (size_t)p * N_ * 3;

    float mn0 = 3.4e38f, mn1 = 3.4e38f, mn2 = 3.4e38f;
    float mx0 = -3.4e38f, mx1 = -3.4e38f, mx2 = -3.4e38f;
    for (int i = t; i < N_; i += 256) {
        float v0 = base[i * 3 + 0], v1 = base[i * 3 + 1], v2 = base[i * 3 + 2];
        mn0 = fminf(mn0, v0); mx0 = fmaxf(mx0, v0);
        mn1 = fminf(mn1, v1); mx1 = fmaxf(mx1, v1);
        mn2 = fminf(mn2, v2); mx2 = fmaxf(mx2, v2);
    }
#pragma unroll
    for (int o = 16; o; o >>= 1) {
        mn0 = fminf(mn0, __shfl_down_sync(0xffffffffu, mn0, o));
        mn1 = fminf(mn1, __shfl_down_sync(0xffffffffu, mn1, o));
        mn2 = fminf(mn2, __shfl_down_sync(0xffffffffu, mn2, o));
        mx0 = fmaxf(mx0, __shfl_down_sync(0xffffffffu, mx0, o));
        mx1 = fmaxf(mx1, __shfl_down_sync(0xffffffffu, mx1, o));
        mx2 = fmaxf(mx2, __shfl_down_sync(0xffffffffu, mx2, o));
    }
    __shared__ float s6[8][6];
    if ((t & 31) == 0) {
        int w = t >> 5;
        s6[w][0] = mn0; s6[w][1] = mn1; s6[w][2] = mn2;
        s6[w][3] = mx0; s6[w][4] = mx1; s6[w][5] = mx2;
    }
    __syncthreads();
    __shared__ float fin[4];
    if (t == 0) {
        float a0 = s6[0][0], a1 = s6[0][1], a2 = s6[0][2];
        float b0 = s6[0][3], b1 = s6[0][4], b2 = s6[0][5];
        for (int w = 1; w < 8; w++) {
            a0 = fminf(a0, s6[w][0]); a1 = fminf(a1, s6[w][1]); a2 = fminf(a2, s6[w][2]);
            b0 = fmaxf(b0, s6[w][3]); b1 = fmaxf(b1, s6[w][4]); b2 = fmaxf(b2, s6[w][5]);
        }
        float d0 = __fsub_rn(b0, a0), d1 = __fsub_rn(b1, a1), d2 = __fsub_rn(b2, a2);
        float diff = fmaxf(fmaxf(d0, d1), d2);
        fin[0] = a0; fin[1] = a1; fin[2] = a2; fin[3] = diff;
        out[VMIN_OFF + p * 3 + 0] = a0;
        out[VMIN_OFF + p * 3 + 1] = a1;
        out[VMIN_OFF + p * 3 + 2] = a2;
        out[DIFF_OFF + p] = diff;
    }
    __syncthreads();
    float vx = fin[0], vy = fin[1], vz = fin[2], df = fin[3];
    for (int i = t; i < N_; i += 256) {
        float* o3 = g_pn + ((size_t)p * N_ + i) * 3;
        o3[0] = __fdiv_rn(__fsub_rn(base[i * 3 + 0], vx), df);
        o3[1] = __fdiv_rn(__fsub_rn(base[i * 3 + 1], vy), df);
        o3[2] = __fdiv_rn(__fsub_rn(base[i * 3 + 2], vz), df);
    }
}

// ---------------------------------------------------------------------------
// Kernel 1b: small pass-through outputs
// ---------------------------------------------------------------------------
__global__ __launch_bounds__(256) void aux_kernel(float* __restrict__ out) {
    int p = blockIdx.x, t = threadIdx.x;
    if (t < 3) out[POSG_OFF + p * 3 + t] = 0.0f;
    if (t == 0) out[BATCHG_OFF + p] = (float)p;
    for (int i = t; i < M2_; i += 256) out[BATCH2_OFF + p * M2_ + i] = (float)p;
    for (int i = t; i < 768; i += 256) out[XG_OFF + p * 768 + i] = 0.0f;
}

// ---------------------------------------------------------------------------
// Kernel 2: FPS — REDUX-based argmax, 256 threads.
// ---------------------------------------------------------------------------
template <int NPTS, int M>
__global__ __launch_bounds__(256) void fps_kernel(int src_sel, float* q_ext) {
    constexpr int T = 256;
    constexpr int U = NPTS / T;
    __shared__ float spx[NPTS], spy[NPTS], spz[NPTS];
    __shared__ u64 wred[8];
    __shared__ int sj;
    int p = blockIdx.x, t = threadIdx.x;
    const float* base = (src_sel ? g_q1 : g_pn) + (size_t)p * NPTS * 3;
    float* q_out = (q_ext ? q_ext : g_q1) + (size_t)p * M * 3;
    for (int i = t; i < NPTS; i += T) {
        spx[i] = base[i * 3 + 0];
        spy[i] = base[i * 3 + 1];
        spz[i] = base[i * 3 + 2];
    }
    __syncthreads();
    float mx[U], my[U], mz[U], d[U];
    float x0 = spx[0], y0 = spy[0], z0 = spz[0];
#pragma unroll
    for (int u = 0; u < U; u++) {
        int i = t + u * T;
        mx[u] = spx[i]; my[u] = spy[i]; mz[u] = spz[i];
        d[u] = dist2e(mx[u], my[u], mz[u], x0, y0, z0);
    }
    if (t == 0) { q_out[0] = x0; q_out[1] = y0; q_out[2] = z0; }
    for (int it = 1; it < M; it++) {
        float bd = d[0]; int bi = t;
#pragma unroll
        for (int u = 1; u < U; u++) {
            if (d[u] > bd) { bd = d[u]; bi = t + u * T; }
        }
        unsigned mb = __reduce_max_sync(0xffffffffu, __float_as_uint(bd));
        int cand = (__float_as_uint(bd) == mb) ? bi : 0x7fffffff;
        int mi = __reduce_min_sync(0xffffffffu, cand);
        if ((t & 31) == 0)
            wred[t >> 5] = ((u64)mb << 32) | (unsigned)(NPTS - mi);
        __syncthreads();
        if (t < 32) {
            u64 b = (t < 8) ? wred[t] : 0ull;
#pragma unroll
            for (int o = 4; o; o >>= 1) {
                u64 v = __shfl_down_sync(0xffffffffu, b, o);
                if (v > b) b = v;
            }
            if (t == 0) sj = NPTS - (int)(unsigned)(b & 0xffffffffull);
        }
        __syncthreads();
        int j = sj;
        float jx = spx[j], jy = spy[j], jz = spz[j];
        if (t == 0) {
            q_out[it * 3 + 0] = jx; q_out[it * 3 + 1] = jy; q_out[it * 3 + 2] = jz;
        }
#pragma unroll
        for (int u = 0; u < U; u++) {
            float nd = dist2e(mx[u], my[u], mz[u], jx, jy, jz);
            d[u] = fminf(d[u], nd);
        }
    }
}

// ---------------------------------------------------------------------------
// Kernel 3: radius top-K — branchless register top-K (no local memory).
// ---------------------------------------------------------------------------
template <int NPTS>
__global__ void nbr_kernel(int src_sel, const float* __restrict__ q_ext,
                           int nq, float r2, int lvl) {
    __shared__ float spx[NPTS], spy[NPTS], spz[NPTS];
    int p = blockIdx.x, t = threadIdx.x;
    const float* base = (src_sel ? g_q1 : g_pn) + (size_t)p * NPTS * 3;
    const float* q = (q_ext ? q_ext : g_q1);
    int* nidx = lvl ? g_nidx2 : g_nidx1;
    int* ncnt = lvl ? g_cnt2 : g_cnt1;
    for (int i = t; i < NPTS; i += blockDim.x) {
        spx[i] = base[i * 3 + 0];
        spy[i] = base[i * 3 + 1];
        spz[i] = base[i * 3 + 2];
    }
    __syncthreads();
    if (t >= nq) return;
    const float* qq = q + ((size_t)p * nq + t) * 3;
    float qx = qq[0], qy = qq[1], qz = qq[2];

    float da[K_];
    int ia[K_];
#pragma unroll
    for (int k = 0; k < K_; k++) { da[k] = 3.4e38f; ia[k] = 0; }
    int cnt = 0;
    float maxd = 3.4e38f;
    int maxslot = 0;

    for (int j = 0; j < NPTS; j++) {
        float d2 = dist2e(spx[j], spy[j], spz[j], qx, qy, qz);
        if (d2 <= r2) {
            if (cnt < K_) {
#pragma unroll
                for (int k = 0; k < K_; k++)
                    if (k == cnt) { da[k] = d2; ia[k] = j; }
                cnt++;
                if (cnt == K_) {
                    float bd = da[0]; int bj = ia[0]; int bs = 0;
#pragma unroll
                    for (int k = 1; k < K_; k++) {
                        bool g = (da[k] > bd) || (da[k] == bd && ia[k] > bj);
                        if (g) { bd = da[k]; bj = ia[k]; bs = k; }
                    }
                    maxd = bd; maxslot = bs;
                }
            } else if (d2 < maxd) {
#pragma unroll
                for (int k = 0; k < K_; k++)
                    if (k == maxslot) { da[k] = d2; ia[k] = j; }
                float bd = da[0]; int bj = ia[0]; int bs = 0;
#pragma unroll
                for (int k = 1; k < K_; k++) {
                    bool g = (da[k] > bd) || (da[k] == bd && ia[k] > bj);
                    if (g) { bd = da[k]; bj = ia[k]; bs = k; }
                }
                maxd = bd; maxslot = bs;
            }
        }
    }
    int* outp = nidx + ((size_t)p * nq + t) * K_;
#pragma unroll
    for (int k = 0; k < K_; k++) outp[k] = (k < cnt) ? ia[k] : 0;
    ncnt[(size_t)p * nq + t] = cnt;
}

// ---------------------------------------------------------------------------
// Kernel 4: MLP1 (6 -> 64 relu -> 128 relu) + masked max — mlp2 template.
// Block = 4 queries, 256 threads. Weights LDG-coalesced, features LDS-bcast.
// ---------------------------------------------------------------------------
__global__ __launch_bounds__(256, 3) void mlp1_kernel(const float* __restrict__ W1a,
                                                      const float* __restrict__ b1a,
                                                      const float* __restrict__ W1b,
                                                      const float* __restrict__ b1b) {
    __shared__ __align__(16) float featT[4 * 6 * 36];    // [lq][i][36]
    __shared__ __align__(16) float h1T[4 * 64 * 36];     // [lq][i][36]
    __shared__ float red[4 * 128 * 2];                   // [lq][c][half]
    __shared__ int scnt[4];
    int b = blockIdx.x, t = threadIdx.x;
    int q0 = b * 4;
    int lq = t >> 6, w = t & 63;
    if (t < 4) scnt[t] = g_cnt1[q0 + t];
    for (int e = t; e < 768; e += 256) {
        int eq = e / 192;
        int rem = e - eq * 192;
        int k = rem / 6, i = rem - k * 6;
        int gq = q0 + eq;
        int p = gq >> 9;
        int j = g_nidx1[(size_t)gq * K_ + k];
        const float* pj = g_pn + ((size_t)p * N_ + j) * 3;
        float v;
        if (i < 3) v = pj[i];
        else       v = pj[i - 3] - g_q1[(size_t)gq * 3 + (i - 3)];
        featT[(eq * 6 + i) * 36 + k] = v;
    }
    __syncthreads();
    // ---- layer 1 ----
    {
        int cp = w & 31, h = w >> 5;
        int c0 = 2 * cp, koff = h * 16;
        float2 bp = *(const float2*)&b1a[c0];
        u64 a0[8], a1[8];
        u64 bx = pack2(bp.x, bp.x), by = pack2(bp.y, bp.y);
#pragma unroll
        for (int m = 0; m < 8; m++) { a0[m] = bx; a1[m] = by; }
#pragma unroll
        for (int i = 0; i < 6; i++) {
            float2 wv = *(const float2*)&W1a[i * 64 + c0];
            u64 w0 = pack2(wv.x, wv.x), w1 = pack2(wv.y, wv.y);
            const ulonglong2* fr = (const ulonglong2*)&featT[(lq * 6 + i) * 36 + koff];
            ulonglong2 fA = fr[0], fB = fr[1], fC = fr[2], fD = fr[3];
            a0[0] = ffma2(fA.x, w0, a0[0]); a0[1] = ffma2(fA.y, w0, a0[1]);
            a0[2] = ffma2(fB.x, w0, a0[2]); a0[3] = ffma2(fB.y, w0, a0[3]);
            a0[4] = ffma2(fC.x, w0, a0[4]); a0[5] = ffma2(fC.y, w0, a0[5]);
            a0[6] = ffma2(fD.x, w0, a0[6]); a0[7] = ffma2(fD.y, w0, a0[7]);
            a1[0] = ffma2(fA.x, w1, a1[0]); a1[1] = ffma2(fA.y, w1, a1[1]);
            a1[2] = ffma2(fB.x, w1, a1[2]); a1[3] = ffma2(fB.y, w1, a1[3]);
            a1[4] = ffma2(fC.x, w1, a1[4]); a1[5] = ffma2(fC.y, w1, a1[5]);
            a1[6] = ffma2(fD.x, w1, a1[6]); a1[7] = ffma2(fD.y, w1, a1[7]);
        }
        float4* h0 = (float4*)&h1T[(lq * 64 + c0) * 36 + koff];
        float4* h1 = (float4*)&h1T[(lq * 64 + c0 + 1) * 36 + koff];
#pragma unroll
        for (int mm = 0; mm < 4; mm++) {
            float2 u0 = unpk(a0[2 * mm]), u1 = unpk(a0[2 * mm + 1]);
            h0[mm] = make_float4(fmaxf(u0.x, 0.f), fmaxf(u0.y, 0.f),
                                 fmaxf(u1.x, 0.f), fmaxf(u1.y, 0.f));
            float2 v0 = unpk(a1[2 * mm]), v1 = unpk(a1[2 * mm + 1]);
            h1[mm] = make_float4(fmaxf(v0.x, 0.f), fmaxf(v0.y, 0.f),
                                 fmaxf(v1.x, 0.f), fmaxf(v1.y, 0.f));
        }
    }
    __syncthreads();
    // ---- layer 2 (2 passes) ----
    int cnt = scnt[lq];
#pragma unroll 1
    for (int pass = 0; pass < 2; pass++) {
        int cp = (w & 31) + pass * 32, h = w >> 5;
        int c0 = 2 * cp, koff = h * 16;
        float2 bp = *(const float2*)&b1b[c0];
        u64 a0[8], a1[8];
        u64 bx = pack2(bp.x, bp.x), by = pack2(bp.y, bp.y);
#pragma unroll
        for (int m = 0; m < 8; m++) { a0[m] = bx; a1[m] = by; }
        for (int i = 0; i < 64; i++) {
            float2 wv = *(const float2*)&W1b[i * 128 + c0];
            u64 w0 = pack2(wv.x, wv.x), w1 = pack2(wv.y, wv.y);
            const ulonglong2* fr = (const ulonglong2*)&h1T[(lq * 64 + i) * 36 + koff];
            ulonglong2 fA = fr[0], fB = fr[1], fC = fr[2], fD = fr[3];
            a0[0] = ffma2(fA.x, w0, a0[0]); a0[1] = ffma2(fA.y, w0, a0[1]);
            a0[2] = ffma2(fB.x, w0, a0[2]); a0[3] = ffma2(fB.y, w0, a0[3]);
            a0[4] = ffma2(fC.x, w0, a0[4]); a0[5] = ffma2(fC.y, w0, a0[5]);
            a0[6] = ffma2(fD.x, w0, a0[6]); a0[7] = ffma2(fD.y, w0, a0[7]);
            a1[0] = ffma2(fA.x, w1, a1[0]); a1[1] = ffma2(fA.y, w1, a1[1]);
            a1[2] = ffma2(fB.x, w1, a1[2]); a1[3] = ffma2(fB.y, w1, a1[3]);
            a1[4] = ffma2(fC.x, w1, a1[4]); a1[5] = ffma2(fC.y, w1, a1[5]);
            a1[6] = ffma2(fD.x, w1, a1[6]); a1[7] = ffma2(fD.y, w1, a1[7]);
        }
        float m0 = 0.f, m1 = 0.f;
#pragma unroll
        for (int m = 0; m < 8; m++) {
            int k0 = koff + 2 * m, k1 = koff + 2 * m + 1;
            float2 u0 = unpk(a0[m]), u1 = unpk(a1[m]);
            if (k0 < cnt) { m0 = fmaxf(m0, fmaxf(u0.x, 0.f)); m1 = fmaxf(m1, fmaxf(u1.x, 0.f)); }
            if (k1 < cnt) { m0 = fmaxf(m0, fmaxf(u0.y, 0.f)); m1 = fmaxf(m1, fmaxf(u1.y, 0.f)); }
        }
        red[(lq * 128 + c0) * 2 + h]     = m0;
        red[(lq * 128 + c0 + 1) * 2 + h] = m1;
    }
    __syncthreads();
    for (int e = t; e < 512; e += 256) {
        int eq = e >> 7, c = e & 127;
        g_x1[(size_t)(q0 + eq) * 128 + c] =
            fmaxf(red[(eq * 128 + c) * 2], red[(eq * 128 + c) * 2 + 1]);
    }
}

// ---------------------------------------------------------------------------
// Kernel 5: MLP2 (131 -> 256 relu -> 384 relu) + masked max — R10 version
// (measured: dup 156us, regs 70, occ 33%). Thread = (ch-pair, 16-nbr half).
// ---------------------------------------------------------------------------
#define MLP2_SMEM ((131 + 256) * 36 * 4)
__global__ __launch_bounds__(256) void mlp2_kernel(const float* __restrict__ q2,
                                                   const float* __restrict__ W2a,
                                                   const float* __restrict__ b2a,
                                                   const float* __restrict__ W2b,
                                                   const float* __restrict__ b2b,
                                                   float* __restrict__ out) {
    extern __shared__ __align__(16) float sm[];
    float* featT = sm;               // [131][36] (k-minor)
    float* h1T   = sm + 131 * 36;    // [256][36]
    __shared__ float red[384 * 2];   // per-(channel, half) masked max
    int q = blockIdx.x;
    int p = q >> 7;
    int t = threadIdx.x;
    int cnt = g_cnt2[q];
    int base_q1 = p * M1_;
    float q2x = q2[q * 3 + 0], q2y = q2[q * 3 + 1], q2z = q2[q * 3 + 2];
    for (int e = t; e < K_ * 131; e += 256) {
        int k = e / 131, i = e - k * 131;
        int j = g_nidx2[q * K_ + k];
        float v;
        if (i < 128) {
            v = g_x1[((size_t)(base_q1 + j)) * 128 + i];
        } else {
            float c = (i == 128) ? q2x : (i == 129) ? q2y : q2z;
            v = g_q1[((size_t)(base_q1 + j)) * 3 + (i - 128)] - c;
        }
        featT[i * 36 + k] = v;
    }
    __syncthreads();
    // -------- layer 1: 256 threads = 128 ch-pairs x 2 neighbor-halves ------
    {
        int cp = t & 127, h = t >> 7;
        int c0 = 2 * cp, koff = h * 16;
        float2 bp = *(const float2*)&b2a[c0];
        u64 a0[8], a1[8];
        u64 bx = pack2(bp.x, bp.x), by = pack2(bp.y, bp.y);
#pragma unroll
        for (int m = 0; m < 8; m++) { a0[m] = bx; a1[m] = by; }
        for (int i = 0; i < 131; i++) {
            float2 wv = *(const float2*)&W2a[i * 256 + c0];
            u64 w0 = pack2(wv.x, wv.x), w1 = pack2(wv.y, wv.y);
            const ulonglong2* fr = (const ulonglong2*)&featT[i * 36 + koff];
            ulonglong2 fA = fr[0], fB = fr[1], fC = fr[2], fD = fr[3];
            a0[0] = ffma2(fA.x, w0, a0[0]); a0[1] = ffma2(fA.y, w0, a0[1]);
            a0[2] = ffma2(fB.x, w0, a0[2]); a0[3] = ffma2(fB.y, w0, a0[3]);
            a0[4] = ffma2(fC.x, w0, a0[4]); a0[5] = ffma2(fC.y, w0, a0[5]);
            a0[6] = ffma2(fD.x, w0, a0[6]); a0[7] = ffma2(fD.y, w0, a0[7]);
            a1[0] = ffma2(fA.x, w1, a1[0]); a1[1] = ffma2(fA.y, w1, a1[1]);
            a1[2] = ffma2(fB.x, w1, a1[2]); a1[3] = ffma2(fB.y, w1, a1[3]);
            a1[4] = ffma2(fC.x, w1, a1[4]); a1[5] = ffma2(fC.y, w1, a1[5]);
            a1[6] = ffma2(fD.x, w1, a1[6]); a1[7] = ffma2(fD.y, w1, a1[7]);
        }
        float4* h0 = (float4*)&h1T[c0 * 36 + koff];
        float4* h1 = (float4*)&h1T[(c0 + 1) * 36 + koff];
#pragma unroll
        for (int mm = 0; mm < 4; mm++) {
            float2 u0 = unpk(a0[2 * mm]), u1 = unpk(a0[2 * mm + 1]);
            h0[mm] = make_float4(fmaxf(u0.x, 0.f), fmaxf(u0.y, 0.f),
                                 fmaxf(u1.x, 0.f), fmaxf(u1.y, 0.f));
            float2 v0 = unpk(a1[2 * mm]), v1 = unpk(a1[2 * mm + 1]);
            h1[mm] = make_float4(fmaxf(v0.x, 0.f), fmaxf(v0.y, 0.f),
                                 fmaxf(v1.x, 0.f), fmaxf(v1.y, 0.f));
        }
    }
    __syncthreads();
    // -------- layer 2: pass A (ch 0..255) + pass B (ch 256..383) -----------
#pragma unroll 1
    for (int pass = 0; pass < 2; pass++) {
        int active = pass == 0 ? 256 : 128;
        if (t < active) {
            int cp, h;
            if (pass == 0) { cp = t & 127; h = t >> 7; }
            else           { cp = t & 63;  h = t >> 6; }
            int c0 = pass * 256 + 2 * cp, koff = h * 16;
            float2 bp = *(const float2*)&b2b[c0];
            u64 a0[8], a1[8];
            u64 bx = pack2(bp.x, bp.x), by = pack2(bp.y, bp.y);
#pragma unroll
            for (int m = 0; m < 8; m++) { a0[m] = bx; a1[m] = by; }
            for (int i = 0; i < 256; i++) {
                float2 wv = *(const float2*)&W2b[i * 384 + c0];
                u64 w0 = pack2(wv.x, wv.x), w1 = pack2(wv.y, wv.y);
                const ulonglong2* fr = (const ulonglong2*)&h1T[i * 36 + koff];
                ulonglong2 fA = fr[0], fB = fr[1], fC = fr[2], fD = fr[3];
                a0[0] = ffma2(fA.x, w0, a0[0]); a0[1] = ffma2(fA.y, w0, a0[1]);
                a0[2] = ffma2(fB.x, w0, a0[2]); a0[3] = ffma2(fB.y, w0, a0[3]);
                a0[4] = ffma2(fC.x, w0, a0[4]); a0[5] = ffma2(fC.y, w0, a0[5]);
                a0[6] = ffma2(fD.x, w0, a0[6]); a0[7] = ffma2(fD.y, w0, a0[7]);
                a1[0] = ffma2(fA.x, w1, a1[0]); a1[1] = ffma2(fA.y, w1, a1[1]);
                a1[2] = ffma2(fB.x, w1, a1[2]); a1[3] = ffma2(fB.y, w1, a1[3]);
                a1[4] = ffma2(fC.x, w1, a1[4]); a1[5] = ffma2(fC.y, w1, a1[5]);
                a1[6] = ffma2(fD.x, w1, a1[6]); a1[7] = ffma2(fD.y, w1, a1[7]);
            }
            float m0 = 0.f, m1 = 0.f;
#pragma unroll
            for (int m = 0; m < 8; m++) {
                int k0 = koff + 2 * m, k1 = koff + 2 * m + 1;
                float2 u0 = unpk(a0[m]), u1 = unpk(a1[m]);
                if (k0 < cnt) { m0 = fmaxf(m0, fmaxf(u0.x, 0.f)); m1 = fmaxf(m1, fmaxf(u1.x, 0.f)); }
                if (k1 < cnt) { m0 = fmaxf(m0, fmaxf(u0.y, 0.f)); m1 = fmaxf(m1, fmaxf(u1.y, 0.f)); }
            }
            red[c0 * 2 + h]       = m0;
            red[(c0 + 1) * 2 + h] = m1;
        }
    }
    __syncthreads();
    for (int e = t; e < 384; e += 256)
        out[X2_OFF + (size_t)q * 384 + e] = fmaxf(red[e * 2], red[e * 2 + 1]);
}

// ---------------------------------------------------------------------------
// Kernel 6: MLP3 (387 -> 512 relu -> 768 relu) + global max pool via atomics
// ---------------------------------------------------------------------------
__global__ __launch_bounds__(256) void mlp3_kernel(const float* __restrict__ W3a,
                                                   const float* __restrict__ b3a,
                                                   const float* __restrict__ W3b,
                                                   const float* __restrict__ b3b,
                                                   float* __restrict__ out) {
    __shared__ __align__(16) float featT[387 * 8];
    __shared__ __align__(16) float hT[512 * 8];
    int b = blockIdx.x, t = threadIdx.x;
    int qbase = b * 8;
    int p = qbase >> 7;
    for (int e = t; e < 8 * 387; e += 256) {
        int qq = e / 387, i = e - qq * 387;
        int q = qbase + qq;
        float v = (i < 384) ? out[X2_OFF + (size_t)q * 384 + i]
                            : out[Q2_OFF + (size_t)q * 3 + (i - 384)];
        featT[i * 8 + qq] = v;
    }
    __syncthreads();
    {
        float bc0 = b3a[t], bc1 = b3a[t + 256];
        u64 s0[4], s1[4];
        u64 p0 = pack2(bc0, bc0), p1 = pack2(bc1, bc1);
#pragma unroll
        for (int m = 0; m < 4; m++) { s0[m] = p0; s1[m] = p1; }
        for (int i = 0; i < 387; i++) {
            float w0f = W3a[i * 512 + t];
            float w1f = W3a[i * 512 + t + 256];
            u64 w0 = pack2(w0f, w0f), w1 = pack2(w1f, w1f);
            const ulonglong2* fr = (const ulonglong2*)&featT[i * 8];
            ulonglong2 fa = fr[0], fb = fr[1];
            s0[0] = ffma2(fa.x, w0, s0[0]); s0[1] = ffma2(fa.y, w0, s0[1]);
            s0[2] = ffma2(fb.x, w0, s0[2]); s0[3] = ffma2(fb.y, w0, s0[3]);
            s1[0] = ffma2(fa.x, w1, s1[0]); s1[1] = ffma2(fa.y, w1, s1[1]);
            s1[2] = ffma2(fb.x, w1, s1[2]); s1[3] = ffma2(fb.y, w1, s1[3]);
        }
        float4* h0 = (float4*)&hT[t * 8];
        float4* h1 = (float4*)&hT[(t + 256) * 8];
        {
            float2 u0 = unpk(s0[0]), u1 = unpk(s0[1]), u2 = unpk(s0[2]), u3 = unpk(s0[3]);
            h0[0] = make_float4(fmaxf(u0.x, 0.f), fmaxf(u0.y, 0.f), fmaxf(u1.x, 0.f), fmaxf(u1.y, 0.f));
            h0[1] = make_float4(fmaxf(u2.x, 0.f), fmaxf(u2.y, 0.f), fmaxf(u3.x, 0.f), fmaxf(u3.y, 0.f));
        }
        {
            float2 u0 = unpk(s1[0]), u1 = unpk(s1[1]), u2 = unpk(s1[2]), u3 = unpk(s1[3]);
            h1[0] = make_float4(fmaxf(u0.x, 0.f), fmaxf(u0.y, 0.f), fmaxf(u1.x, 0.f), fmaxf(u1.y, 0.f));
            h1[1] = make_float4(fmaxf(u2.x, 0.f), fmaxf(u2.y, 0.f), fmaxf(u3.x, 0.f), fmaxf(u3.y, 0.f));
        }
    }
    __syncthreads();
    {
        float bc0 = b3b[t], bc1 = b3b[t + 256], bc2 = b3b[t + 512];
        u64 s0[4], s1[4], s2[4];
        u64 p0 = pack2(bc0, bc0), p1 = pack2(bc1, bc1), p2 = pack2(bc2, bc2);
#pragma unroll
        for (int m = 0; m < 4; m++) { s0[m] = p0; s1[m] = p1; s2[m] = p2; }
        for (int i = 0; i < 512; i++) {
            float w0f = W3b[i * 768 + t];
            float w1f = W3b[i * 768 + t + 256];
            float w2f = W3b[i * 768 + t + 512];
            u64 w0 = pack2(w0f, w0f), w1 = pack2(w1f, w1f), w2 = pack2(w2f, w2f);
            const ulonglong2* hr = (const ulonglong2*)&hT[i * 8];
            ulonglong2 fa = hr[0], fb = hr[1];
            s0[0] = ffma2(fa.x, w0, s0[0]); s0[1] = ffma2(fa.y, w0, s0[1]);
            s0[2] = ffma2(fb.x, w0, s0[2]); s0[3] = ffma2(fb.y, w0, s0[3]);
            s1[0] = ffma2(fa.x, w1, s1[0]); s1[1] = ffma2(fa.y, w1, s1[1]);
            s1[2] = ffma2(fb.x, w1, s1[2]); s1[3] = ffma2(fb.y, w1, s1[3]);
            s2[0] = ffma2(fa.x, w2, s2[0]); s2[1] = ffma2(fa.y, w2, s2[1]);
            s2[2] = ffma2(fb.x, w2, s2[2]); s2[3] = ffma2(fb.y, w2, s2[3]);
        }
        float m0 = 0.f, m1 = 0.f, m2 = 0.f;
#pragma unroll
        for (int m = 0; m < 4; m++) {
            float2 u0 = unpk(s0[m]), u1 = unpk(s1[m]), u2 = unpk(s2[m]);
            m0 = fmaxf(m0, fmaxf(fmaxf(u0.x, 0.f), fmaxf(u0.y, 0.f)));
            m1 = fmaxf(m1, fmaxf(fmaxf(u1.x, 0.f), fmaxf(u1.y, 0.f)));
            m2 = fmaxf(m2, fmaxf(fmaxf(u2.x, 0.f), fmaxf(u2.y, 0.f)));
        }
        atomicMax((unsigned*)&out[XG_OFF + (size_t)p * 768 + t], __float_as_uint(m0));
        atomicMax((unsigned*)&out[XG_OFF + (size_t)p * 768 + t + 256], __float_as_uint(m1));
        atomicMax((unsigned*)&out[XG_OFF + (size_t)p * 768 + t + 512], __float_as_uint(m2));
    }
}

// ---------------------------------------------------------------------------
// Launch. Instrumentation dup removed (it cost its full duration in the timed
// region). ncu slot 3 now profiles nbr_kernel<2048>.
// ---------------------------------------------------------------------------
extern "C" void kernel_launch(void* const* d_in, const int* in_sizes, int n_in,
                              void* d_out, int out_size) {
    const float* pos = (const float*)d_in[0];
    const float* W1a = (const float*)d_in[2];
    const float* b1a = (const float*)d_in[3];
    const float* W1b = (const float*)d_in[4];
    const float* b1b = (const float*)d_in[5];
    const float* W2a = (const float*)d_in[6];
    const float* b2a = (const float*)d_in[7];
    const float* W2b = (const float*)d_in[8];
    const float* b2b = (const float*)d_in[9];
    const float* W3a = (const float*)d_in[10];
    const float* b3a = (const float*)d_in[11];
    const float* W3b = (const float*)d_in[12];
    const float* b3b = (const float*)d_in[13];
    float* out = (float*)d_out;

    const float R1SQ = (float)(0.15 * 0.15);
    const float R2SQ = (float)(0.3 * 0.3);

    static bool attr_set = false;
    if (!attr_set) {
        cudaFuncSetAttribute(mlp2_kernel, cudaFuncAttributeMaxDynamicSharedMemorySize,
                             MLP2_SMEM);
        attr_set = true;
    }

    norm_kernel<<<P_, 256>>>(pos, out);                              // 0
    aux_kernel<<<P_, 256>>>(out);                                    // 1
    fps_kernel<N_, M1_><<<P_, 256>>>(0, nullptr);                    // 2
    nbr_kernel<N_><<<P_, 512>>>(0, nullptr, M1_, R1SQ, 0);           // 3 <- profiled
    mlp1_kernel<<<P_ * M1_ / 4, 256>>>(W1a, b1a, W1b, b1b);          // 4
    fps_kernel<M1_, M2_><<<P_, 256>>>(1, out + Q2_OFF);              // 5
    nbr_kernel<M1_><<<P_, 128>>>(1, out + Q2_OFF, M2_, R2SQ, 1);     // 6
    mlp2_kernel<<<P_ * M2_, 256, MLP2_SMEM>>>(out + Q2_OFF, W2a, b2a, W2b, b2b, out); // 7
    mlp3_kernel<<<P_ * M2_ / 8, 256>>>(W3a, b3a, W3b, b3b, out);     // 8
}